// round 3
// baseline (speedup 1.0000x reference)
#include <cuda_runtime.h>

#define N_PH 1024
#define IMG_H 256
#define IMG_W 256
#define NPIX (IMG_H * IMG_W)
#define BATCH 2

// Constants from the reference
#define C_SPREAD   0.000675f
#define C_R2S      0.5f
#define C_SLOPE    19152642.5f
#define C_HALF     1.057e-07f
#define C_RHEO     2.39e-05f
#define C_FREQ     300.0f
#define C_PW       0.00017f
#define C_ISCALE   8e-05f
#define CUT_ARG    20.0f        // exp(-20) = 2e-9, far below 1e-3 rel-err budget

// Scratch accumulator. __device__ globals are zero-initialized at module load;
// finalize_kernel resets it to zero after every pass so each graph replay
// starts from a clean state (deterministic, allocation-free).
__device__ float g_acc[BATCH * NPIX];

__global__ void __launch_bounds__(128)
scatter_kernel(const float* __restrict__ stim,
               const float* __restrict__ vx,
               const float* __restrict__ vy,
               const float* __restrict__ Marr,
               const float* __restrict__ px,
               const float* __restrict__ py,
               const int*   __restrict__ idx)
{
    const int bn = blockIdx.x;          // 0..2047
    const int n  = bn & (N_PH - 1);
    const int b  = bn >> 10;

    // fov = px.max() = last element of the monotonically increasing linspace
    const float fov      = px[NPIX - 1];
    const float deg2pix  = (float)IMG_W / (fov * 2.0f);

    // Per-phosphene activation
    const float I    = stim[b * N_PH + idx[n]] * C_ISCALE;
    float Ieff       = I - C_RHEO; if (Ieff < 0.0f) Ieff = 0.0f;
    const float Q    = Ieff * (C_PW * C_FREQ);
    const float t    = C_SLOPE * (Q - C_HALF);
    const float Bw   = 1.0f / (1.0f + __expf(-t));
    if (Bw < 1e-7f) return;             // contribution below error budget

    const float size_base = sqrtf(I / C_SPREAD);
    float sigma_px = size_base * (C_R2S / Marr[n]) * deg2pix;
    if (sigma_px < 1.0f) sigma_px = 1.0f;
    const float inv2s2 = 1.0f / (2.0f * sigma_px * sigma_px);

    // Footprint: dist2*inv2s2 <= CUT_ARG  =>  r_px <= sqrt(2*CUT_ARG)*sigma
    const float rad_px  = sqrtf(CUT_ARG / inv2s2);
    const float rad_deg = rad_px / deg2pix;

    const float cx = vx[n], cy = vy[n];
    const float step = (2.0f * fov) / (float)(IMG_W - 1);   // linspace spacing

    int jlo = (int)floorf((cx - rad_deg + fov) / step) - 1;
    int jhi = (int)ceilf ((cx + rad_deg + fov) / step) + 1;
    int ilo = (int)floorf((cy - rad_deg + fov) / step) - 1;
    int ihi = (int)ceilf ((cy + rad_deg + fov) / step) + 1;
    if (jlo < 0) jlo = 0;
    if (ilo < 0) ilo = 0;
    if (jhi > IMG_W - 1) jhi = IMG_W - 1;
    if (ihi > IMG_H - 1) ihi = IMG_H - 1;
    const int nx = jhi - jlo + 1;
    const int ny = ihi - ilo + 1;
    if (nx <= 0 || ny <= 0) return;

    float* __restrict__ acc = g_acc + b * NPIX;
    const int total = nx * ny;
    for (int tix = threadIdx.x; tix < total; tix += blockDim.x) {
        const int w = jlo + tix % nx;
        const int h = ilo + tix / nx;
        // Use the ACTUAL grid values so coordinates match the reference exactly:
        // px[h][w] depends only on w (row 0), py[h][w] only on h (column 0).
        const float dx = (px[w]           - cx) * deg2pix;
        const float dy = (py[h * IMG_W]   - cy) * deg2pix;
        const float arg = (dx * dx + dy * dy) * inv2s2;
        if (arg < CUT_ARG) {
            atomicAdd(&acc[h * IMG_W + w], __expf(-arg) * Bw);
        }
    }
}

__global__ void __launch_bounds__(256)
finalize_kernel(float* __restrict__ out)
{
    const int i = blockIdx.x * blockDim.x + threadIdx.x;
    if (i < BATCH * NPIX) {
        float v = 2.0f * g_acc[i];
        g_acc[i] = 0.0f;                     // reset for next graph replay
        v = v < 0.0f ? 0.0f : (v > 1.0f ? 1.0f : v);
        out[i] = v;
    }
}

extern "C" void kernel_launch(void* const* d_in, const int* in_sizes, int n_in,
                              void* d_out, int out_size)
{
    const float* stim = (const float*)d_in[0];   // [2,32,32]
    const float* vx   = (const float*)d_in[1];   // [1024]
    const float* vy   = (const float*)d_in[2];   // [1024]
    const float* M    = (const float*)d_in[3];   // [1024]
    const float* px   = (const float*)d_in[4];   // [256,256]
    const float* py   = (const float*)d_in[5];   // [256,256]
    const int*   idx  = (const int*)  d_in[6];   // [1024]
    float* out = (float*)d_out;                  // [2,1,256,256]

    scatter_kernel<<<BATCH * N_PH, 128>>>(stim, vx, vy, M, px, py, idx);
    finalize_kernel<<<(BATCH * NPIX + 255) / 256, 256>>>(out);
}

// round 4
// speedup vs baseline: 1.1910x; 1.1910x over previous
#include <cuda_runtime.h>

#define N_PH  1024
#define IMG   256
#define NPIX  (IMG * IMG)
#define TW    32          // tile width  (pixels)
#define TH    8           // tile height (pixels)
#define CAP   512         // max survivors per tile (analysis bound ~150)

// Constants from the reference
#define C_SPREAD_INV  (1.0f / 0.000675f)
#define C_R2S         0.5f
#define C_SLOPE       19152642.5f
#define C_HALF        1.057e-07f
#define C_RHEO        2.39e-05f
#define C_PWF         (0.00017f * 300.0f)
#define C_ISCALE      8e-05f
#define NEG_HALF_LOG2E 0.72134752f   // log2(e)/2; m = -this / sigma_px^2

__global__ void __launch_bounds__(256)
fused_kernel(const float* __restrict__ stim,
             const float* __restrict__ vx,
             const float* __restrict__ vy,
             const float* __restrict__ Marr,
             const float* __restrict__ px,
             const float* __restrict__ py,
             const int*   __restrict__ idx,
             float*       __restrict__ out)
{
    __shared__ float4 sh[CAP];
    __shared__ int    cnt;

    const int tid  = threadIdx.x;
    const int bx   = blockIdx.x;           // 0..511
    const int b    = bx >> 8;              // batch
    const int tile = bx & 255;             // 8 x-tiles * 32 y-tiles
    const int tx0  = (tile & 7)  * TW;
    const int ty0  = (tile >> 3) * TH;

    if (tid == 0) cnt = 0;

    // fov = px.max() = last element of ascending linspace
    const float fov = px[NPIX - 1];
    const float d2p = (float)IMG / (2.0f * fov);   // deg2pix

    // Scaled pixel coordinate of column w: px[w]*d2p == w*(256/255) - 128 (±ulp).
    // Margin is absorbed by the inflated rad2 below.
    const float PSTEP = 256.0f / 255.0f;
    const float bxlo = tx0 * PSTEP - 128.0f;
    const float bxhi = (tx0 + TW - 1) * PSTEP - 128.0f;
    const float bylo = ty0 * PSTEP - 128.0f;
    const float byhi = (ty0 + TH - 1) * PSTEP - 128.0f;

    __syncthreads();   // cnt visible

    // ---- Phase 1: compact the phosphenes whose footprint touches this tile ----
    const float* stimb = stim + b * N_PH;
    for (int n = tid; n < N_PH; n += 256) {
        const float I   = stimb[idx[n]] * C_ISCALE;
        const float cxs = vx[n] * d2p;
        const float cys = vy[n] * d2p;

        // sigma_px^2 = max( (I/SPREAD) * (R2S/M * deg2pix)^2 , 1 )
        const float invMs = (C_R2S / Marr[n]) * d2p;
        float sp2 = (I * C_SPREAD_INV) * invMs * invMs;
        sp2 = fmaxf(sp2, 1.0f);

        // Conservative footprint: rad^2 = 70*sigma^2  (cut at arg~35, e^-35 tail,
        // with >2px slack over the coordinate approximation above).
        const float rad2 = 70.0f * sp2;
        const float ddx = fmaxf(fmaxf(bxlo - cxs, cxs - bxhi), 0.0f);
        const float ddy = fmaxf(fmaxf(bylo - cys, cys - byhi), 0.0f);
        if (ddx * ddx + ddy * ddy > rad2) continue;

        // Brightness weight (x2 output scale folded in)
        const float Ieff = fmaxf(I - C_RHEO, 0.0f);
        const float t    = C_SLOPE * (Ieff * C_PWF - C_HALF);
        const float Bw2  = 2.0f / (1.0f + __expf(-t));

        const float m = -NEG_HALF_LOG2E / sp2;   // exp(-d2/2s2) = exp2(d2*m)

        const int p = atomicAdd(&cnt, 1);
        if (p < CAP) sh[p] = make_float4(cxs, cys, m, Bw2);
    }
    __syncthreads();

    // ---- Phase 2: one pixel per thread, register accumulation ----
    const int w = tx0 + (tid & 31);
    const int h = ty0 + (tid >> 5);
    // Exact grid values (match reference bit-level coordinates):
    // px[y][x] depends only on x (row 0); py[y][x] only on y (col 0).
    const float pxs = px[w] * d2p;
    const float pys = py[h * IMG] * d2p;

    const int nsv = min(cnt, CAP);
    float acc = 0.0f;
    #pragma unroll 4
    for (int i = 0; i < nsv; i++) {
        const float4 f = sh[i];
        const float dx = pxs - f.x;
        const float dy = pys - f.y;
        const float d2 = fmaf(dx, dx, dy * dy);
        acc += f.w * exp2f(d2 * f.z);    // full gaussian, no cutoff branch
    }

    out[b * NPIX + h * IMG + w] = fminf(acc, 1.0f);  // acc >= 0 always
}

extern "C" void kernel_launch(void* const* d_in, const int* in_sizes, int n_in,
                              void* d_out, int out_size)
{
    const float* stim = (const float*)d_in[0];   // [2,32,32]
    const float* vx   = (const float*)d_in[1];   // [1024]
    const float* vy   = (const float*)d_in[2];   // [1024]
    const float* M    = (const float*)d_in[3];   // [1024]
    const float* px   = (const float*)d_in[4];   // [256,256]
    const float* py   = (const float*)d_in[5];   // [256,256]
    const int*   idx  = (const int*)  d_in[6];   // [1024]
    float* out = (float*)d_out;                  // [2,1,256,256]

    fused_kernel<<<2 * (IMG / TW) * (IMG / TH), 256>>>(stim, vx, vy, M, px, py, idx, out);
}